// round 4
// baseline (speedup 1.0000x reference)
#include <cuda_runtime.h>
#include <cuda_bf16.h>
#include <math.h>

#define NRES 768
#define HN   12
#define CH   16
#define CZ   128
#define PQN  4
#define PVN  8
#define CS   384

// ---------------- scratch (device globals; no allocation) ----------------
__device__ float g_q   [NRES * HN * CH];          // [n][h*16+c]
__device__ float g_kv  [NRES * HN * 2 * CH];      // [n][h*32+c] (k: c<16, v: c>=16)
__device__ float g_qp  [NRES * HN * PQN * 3];     // raw qp proj  [n][144]
__device__ float g_kvp [NRES * HN * 12 * 3];      // raw kvp proj [n][432]
__device__ float g_qpts[NRES * HN * PQN * 3];     // [n][h*12 + p*3 + i]
__device__ float g_kpts[NRES * HN * PQN * 3];     // [n][h*12 + p*3 + i]
__device__ float g_vpts[NRES * HN * PVN * 3];     // [n][h*24 + p*3 + i]
__device__ float g_a   [HN * NRES * NRES];        // [h][n][m]
__device__ float g_obuf[NRES * HN * 40];          // [n][h][c] c<16: o ; 16..39: o_pt global
__device__ float g_ocat[NRES * 2112];             // concat features per n

// ---------------- generic tiled GEMM: C = A (M x K) * W^T (Nc x K) + bias --
// M fixed 768 (divisible by 64), K divisible by 32, Nc guarded.
__global__ void gemm_abt(const float* __restrict__ A, const float* __restrict__ W,
                         const float* __restrict__ bias, float* __restrict__ C,
                         int Nc, int K) {
    __shared__ float As[32][68];
    __shared__ float Bs[32][68];
    const int bm = blockIdx.y * 64;
    const int bn = blockIdx.x * 64;
    const int tid = threadIdx.x;
    const int ty = tid >> 4, tx = tid & 15;
    float acc[4][4];
#pragma unroll
    for (int i = 0; i < 4; i++)
#pragma unroll
        for (int j = 0; j < 4; j++) acc[i][j] = 0.f;

    for (int k0 = 0; k0 < K; k0 += 32) {
#pragma unroll
        for (int i = 0; i < 8; i++) {
            int idx = tid + i * 256;
            int r = idx >> 5, c = idx & 31;
            As[c][r] = A[(size_t)(bm + r) * K + k0 + c];
            int j = bn + r;
            Bs[c][r] = (j < Nc) ? W[(size_t)j * K + k0 + c] : 0.f;
        }
        __syncthreads();
#pragma unroll
        for (int kk = 0; kk < 32; kk++) {
            float ra[4], rb[4];
#pragma unroll
            for (int i = 0; i < 4; i++) ra[i] = As[kk][ty * 4 + i];
#pragma unroll
            for (int j = 0; j < 4; j++) rb[j] = Bs[kk][tx * 4 + j];
#pragma unroll
            for (int i = 0; i < 4; i++)
#pragma unroll
                for (int j = 0; j < 4; j++) acc[i][j] += ra[i] * rb[j];
        }
        __syncthreads();
    }
#pragma unroll
    for (int i = 0; i < 4; i++) {
        int m = bm + ty * 4 + i;
#pragma unroll
        for (int j = 0; j < 4; j++) {
            int jj = bn + tx * 4 + j;
            if (jj < Nc) C[(size_t)m * Nc + jj] = acc[i][j] + bias[jj];
        }
    }
}

// ---------------- point transform: rotate+translate projected points -------
__global__ void k_points(const float* __restrict__ rot, const float* __restrict__ trans) {
    int n = blockIdx.x;
    int t = threadIdx.x;   // 192 threads
    const float* r = rot + n * 9;
    float t0 = trans[n * 3 + 0], t1 = trans[n * 3 + 1], t2 = trans[n * 3 + 2];
    if (t < 48) {
        // q point index t = h*4 + p ; coords at g_qp[n*144 + j*48 + t]
        float x = g_qp[n * 144 + t];
        float y = g_qp[n * 144 + 48 + t];
        float z = g_qp[n * 144 + 96 + t];
        float o0 = r[0] * x + r[1] * y + r[2] * z + t0;
        float o1 = r[3] * x + r[4] * y + r[5] * z + t1;
        float o2 = r[6] * x + r[7] * y + r[8] * z + t2;
        g_qpts[n * 144 + t * 3 + 0] = o0;
        g_qpts[n * 144 + t * 3 + 1] = o1;
        g_qpts[n * 144 + t * 3 + 2] = o2;
    } else {
        int p = t - 48;  // 0..143 = h*12 + pp
        float x = g_kvp[n * 432 + p];
        float y = g_kvp[n * 432 + 144 + p];
        float z = g_kvp[n * 432 + 288 + p];
        float o0 = r[0] * x + r[1] * y + r[2] * z + t0;
        float o1 = r[3] * x + r[4] * y + r[5] * z + t1;
        float o2 = r[6] * x + r[7] * y + r[8] * z + t2;
        int h = p / 12, pp = p % 12;
        if (pp < 4) {
            int base = n * 144 + (h * 4 + pp) * 3;
            g_kpts[base + 0] = o0; g_kpts[base + 1] = o1; g_kpts[base + 2] = o2;
        } else {
            int base = n * 288 + (h * 8 + (pp - 4)) * 3;
            g_vpts[base + 0] = o0; g_vpts[base + 1] = o1; g_vpts[base + 2] = o2;
        }
    }
}

// ---------------- bmat pass: a[h][n][m] = sqrt(1/3)*(z[n,m]·w_b[h] + b_b[h])
__global__ void k_bmat(const float* __restrict__ z, const float* __restrict__ w_b,
                       const float* __restrict__ b_b) {
    __shared__ float zsh[64 * 129];
    __shared__ float wsh[12 * 129];
    const int n = blockIdx.x;
    const int mt = blockIdx.y;            // tile of 64 m
    const int tid = threadIdx.x;
    const float* zp = z + ((size_t)n * NRES + mt * 64) * CZ;
    for (int idx = tid; idx < 64 * 128; idx += 256) {
        int m = idx >> 7, c = idx & 127;
        zsh[m * 129 + c] = zp[idx];
    }
    for (int idx = tid; idx < 12 * 128; idx += 256) {
        int h = idx >> 7, c = idx & 127;
        wsh[h * 129 + c] = w_b[idx];
    }
    __syncthreads();
    for (int task = tid; task < 768; task += 256) {
        int h = task / 64, m = task & 63;
        const float* zr = &zsh[m * 129];
        const float* wr = &wsh[h * 129];
        float acc = 0.f;
#pragma unroll 8
        for (int c = 0; c < 128; c++) acc += zr[c] * wr[c];
        g_a[((size_t)h * NRES + n) * NRES + mt * 64 + m] =
            0.5773502691896258f * (acc + b_b[h]);
    }
}

// ---------------- logits add: qk + point-attn + mask (in place on g_a) -----
__global__ void k_logits(const float* __restrict__ mask,
                         const float* __restrict__ head_weights) {
    __shared__ float ksh[256 * 17];    // k[m][16] pad 17
    __shared__ float kpsh[256 * 13];   // k_pts[m][12] pad 13
    __shared__ float msh[256];
    const int h = blockIdx.x;
    const int n0 = blockIdx.y * 32;
    const int tid = threadIdx.x;
    const int row = tid >> 4;          // 0..15 -> two n each
    const int mcol = tid & 15;

    const int nA = n0 + row * 2, nB = nA + 1;
    float qA[16], qB[16], pA[12], pB[12];
#pragma unroll
    for (int c = 0; c < 16; c++) {
        qA[c] = g_q[nA * 192 + h * 16 + c];
        qB[c] = g_q[nB * 192 + h * 16 + c];
    }
#pragma unroll
    for (int c = 0; c < 12; c++) {
        pA[c] = g_qpts[nA * 144 + h * 12 + c];
        pB[c] = g_qpts[nB * 144 + h * 12 + c];
    }
    const float maskA = mask[nA], maskB = mask[nB];
    const float s1 = 0.14433756729740643f;                 // sqrt(1/48)
    const float hw = log1pf(expf(head_weights[h]));
    const float wpt = -0.5f * hw * 0.13608276348795434f;   // sqrt(1/54)

    for (int mt = 0; mt < 3; mt++) {
        const int mbase = mt * 256;
        __syncthreads();
        for (int idx = tid; idx < 256 * 16; idx += 256) {
            int m = idx >> 4, c = idx & 15;
            ksh[m * 17 + c] = g_kv[(size_t)(mbase + m) * 384 + h * 32 + c];
        }
        for (int idx = tid; idx < 256 * 12; idx += 256) {
            int m = idx / 12, c = idx % 12;
            kpsh[m * 13 + c] = g_kpts[(mbase + m) * 144 + h * 12 + c];
        }
        if (tid < 256) msh[tid] = mask[mbase + tid];
        __syncthreads();
#pragma unroll 1
        for (int kk = 0; kk < 16; kk++) {
            int ml = mcol + kk * 16;
            const float* kr = &ksh[ml * 17];
            const float* kp = &kpsh[ml * 13];
            float qkA = 0.f, qkB = 0.f;
#pragma unroll
            for (int c = 0; c < 16; c++) { float kv = kr[c]; qkA += qA[c] * kv; qkB += qB[c] * kv; }
            float ptA = 0.f, ptB = 0.f;
#pragma unroll
            for (int c = 0; c < 12; c++) {
                float kv = kp[c];
                float dA = pA[c] - kv; ptA += dA * dA;
                float dB = pB[c] - kv; ptB += dB * dB;
            }
            float mm = msh[ml];
            float addA = qkA * s1 + wpt * ptA + (maskA * mm - 1.f) * 100000.f;
            float addB = qkB * s1 + wpt * ptB + (maskB * mm - 1.f) * 100000.f;
            size_t iA = ((size_t)h * NRES + nA) * NRES + mbase + ml;
            size_t iB = ((size_t)h * NRES + nB) * NRES + mbase + ml;
            g_a[iA] += addA;
            g_a[iB] += addB;
        }
    }
}

// ---------------- softmax over m (row = h*768 + n) --------------------------
__global__ void k_softmax() {
    __shared__ float red[256];
    const size_t row = blockIdx.x;
    float* a = g_a + row * NRES;
    const int t = threadIdx.x;
    float v0 = a[t], v1 = a[t + 256], v2 = a[t + 512];
    float mx = fmaxf(v0, fmaxf(v1, v2));
    red[t] = mx; __syncthreads();
    for (int s = 128; s > 0; s >>= 1) {
        if (t < s) red[t] = fmaxf(red[t], red[t + s]);
        __syncthreads();
    }
    mx = red[0];
    __syncthreads();
    v0 = expf(v0 - mx); v1 = expf(v1 - mx); v2 = expf(v2 - mx);
    red[t] = v0 + v1 + v2; __syncthreads();
    for (int s = 128; s > 0; s >>= 1) {
        if (t < s) red[t] += red[t + s];
        __syncthreads();
    }
    float inv = 1.f / red[0];
    a[t] = v0 * inv; a[t + 256] = v1 * inv; a[t + 512] = v2 * inv;
}

// ---------------- o = a@v, o_pt = a@v_pts (global frame) --------------------
// block: (h, 64-n tile). per-thread micro tile: 4 n x 3 c (c stride 16).
__global__ void k_av() {
    __shared__ float ash[64 * 65];
    __shared__ float vsh[64 * 48];   // 40 data cols + pad to 48 (keeps speculative reads in-bounds)
    const int h = blockIdx.x;
    const int n0 = blockIdx.y * 64;
    const int tid = threadIdx.x;
    const int nq = tid & 15, cg = tid >> 4;   // 16 x 16
    float acc[4][3];
#pragma unroll
    for (int i = 0; i < 4; i++)
#pragma unroll
        for (int j = 0; j < 3; j++) acc[i][j] = 0.f;

    for (int mt = 0; mt < 12; mt++) {
        const int m0 = mt * 64;
        __syncthreads();
        for (int idx = tid; idx < 4096; idx += 256) {
            int nn = idx >> 6, mm = idx & 63;
            ash[nn * 65 + mm] = g_a[((size_t)h * NRES + n0 + nn) * NRES + m0 + mm];
        }
        for (int idx = tid; idx < 64 * 48; idx += 256) {
            int mm = idx / 48, c = idx % 48;
            float v = 0.f;
            if (c < 16)      v = g_kv[(size_t)(m0 + mm) * 384 + h * 32 + 16 + c];
            else if (c < 40) v = g_vpts[(m0 + mm) * 288 + h * 24 + (c - 16)];
            vsh[mm * 48 + c] = v;
        }
        __syncthreads();
#pragma unroll 4
        for (int mm = 0; mm < 64; mm++) {
            float ra[4], rv[3];
#pragma unroll
            for (int i = 0; i < 4; i++) ra[i] = ash[(nq + 16 * i) * 65 + mm];
#pragma unroll
            for (int j = 0; j < 3; j++) rv[j] = vsh[mm * 48 + cg + 16 * j];
#pragma unroll
            for (int i = 0; i < 4; i++)
#pragma unroll
                for (int j = 0; j < 3; j++) acc[i][j] += ra[i] * rv[j];
        }
    }
#pragma unroll
    for (int i = 0; i < 4; i++) {
        int n = n0 + nq + 16 * i;
#pragma unroll
        for (int j = 0; j < 3; j++) {
            int c = cg + 16 * j;
            if (c < 40) g_obuf[((size_t)n * 12 + h) * 40 + c] = acc[i][j];
        }
    }
}

// ---------------- o_pair = a @ z (second z pass) -----------------------------
__global__ void k_opair(const float* __restrict__ z) {
    __shared__ float ash[12 * 768];
    const int n = blockIdx.x;
    const int tid = threadIdx.x;
    for (int idx = tid; idx < 12 * 768; idx += 256) {
        int h = idx / 768, m = idx % 768;
        ash[idx] = g_a[((size_t)h * NRES + n) * NRES + m];
    }
    __syncthreads();
    const int c = tid & 127;
    const int half = tid >> 7;
    const float* zp = z + ((size_t)n * NRES + half * 384) * CZ + c;
    float acc[12];
#pragma unroll
    for (int h = 0; h < 12; h++) acc[h] = 0.f;
    const float* ab = ash + half * 384;
#pragma unroll 4
    for (int m = 0; m < 384; m++) {
        float zv = zp[(size_t)m * CZ];
#pragma unroll
        for (int h = 0; h < 12; h++) acc[h] += ab[h * 768 + m] * zv;
    }
    __syncthreads();
    if (half == 1) {
#pragma unroll
        for (int h = 0; h < 12; h++) ash[h * 128 + c] = acc[h];
    }
    __syncthreads();
    if (half == 0) {
#pragma unroll
        for (int h = 0; h < 12; h++) {
            float o = acc[h] + ash[h * 128 + c];
            g_ocat[(size_t)n * 2112 + 576 + h * 128 + c] = o;
        }
    }
}

// ---------------- finalize: o_pt to local frame, norms, concat --------------
__global__ void k_finish(const float* __restrict__ rot, const float* __restrict__ trans) {
    const int n = blockIdx.x;
    const int t = threadIdx.x;   // 192
    if (t < 96) {
        int h = t >> 3, p = t & 7;
        const float* ob = &g_obuf[((size_t)n * 12 + h) * 40 + 16 + p * 3];
        float gx = ob[0] - trans[n * 3 + 0];
        float gy = ob[1] - trans[n * 3 + 1];
        float gz = ob[2] - trans[n * 3 + 2];
        const float* r = rot + n * 9;
        float lx = r[0] * gx + r[3] * gy + r[6] * gz;
        float ly = r[1] * gx + r[4] * gy + r[7] * gz;
        float lz = r[2] * gx + r[5] * gy + r[8] * gz;
        size_t base = (size_t)n * 2112;
        g_ocat[base + 192 + t] = lx;
        g_ocat[base + 288 + t] = ly;
        g_ocat[base + 384 + t] = lz;
        g_ocat[base + 480 + t] = sqrtf(lx * lx + ly * ly + lz * lz + 1e-8f);
    }
    // o channels (192)
    g_ocat[(size_t)n * 2112 + t] = g_obuf[((size_t)n * 12 + (t >> 4)) * 40 + (t & 15)];
}

// ---------------- launcher ---------------------------------------------------
extern "C" void kernel_launch(void* const* d_in, const int* in_sizes, int n_in,
                              void* d_out, int out_size) {
    const float* s      = (const float*)d_in[0];
    const float* z      = (const float*)d_in[1];
    const float* rot    = (const float*)d_in[2];
    const float* trans  = (const float*)d_in[3];
    const float* mask   = (const float*)d_in[4];
    const float* w_q    = (const float*)d_in[5];
    const float* b_q    = (const float*)d_in[6];
    const float* w_kv   = (const float*)d_in[7];
    const float* b_kv   = (const float*)d_in[8];
    const float* w_qp   = (const float*)d_in[9];
    const float* b_qp   = (const float*)d_in[10];
    const float* w_kvp  = (const float*)d_in[11];
    const float* b_kvp  = (const float*)d_in[12];
    const float* w_b    = (const float*)d_in[13];
    const float* b_b    = (const float*)d_in[14];
    const float* hwts   = (const float*)d_in[15];
    const float* w_out  = (const float*)d_in[16];
    const float* b_out  = (const float*)d_in[17];
    float* out = (float*)d_out;

    float *pq, *pkv, *pqp, *pkvp, *pocat;
    cudaGetSymbolAddress((void**)&pq,    g_q);
    cudaGetSymbolAddress((void**)&pkv,   g_kv);
    cudaGetSymbolAddress((void**)&pqp,   g_qp);
    cudaGetSymbolAddress((void**)&pkvp,  g_kvp);
    cudaGetSymbolAddress((void**)&pocat, g_ocat);

    // projections
    gemm_abt<<<dim3(3, 12), 256>>>(s, w_q,   b_q,   pq,   192, 384);
    gemm_abt<<<dim3(6, 12), 256>>>(s, w_kv,  b_kv,  pkv,  384, 384);
    gemm_abt<<<dim3(3, 12), 256>>>(s, w_qp,  b_qp,  pqp,  144, 384);
    gemm_abt<<<dim3(7, 12), 256>>>(s, w_kvp, b_kvp, pkvp, 432, 384);
    // point transform
    k_points<<<NRES, 192>>>(rot, trans);
    // logits: bmat (z pass 1), then qk + pt + mask
    k_bmat<<<dim3(NRES, 12), 256>>>(z, w_b, b_b);
    k_logits<<<dim3(12, 24), 256>>>(mask, hwts);
    // softmax
    k_softmax<<<HN * NRES, 256>>>();
    // attention outputs
    k_av<<<dim3(12, 12), 256>>>();
    k_opair<<<NRES, 256>>>(z);   // z pass 2
    k_finish<<<NRES, 192>>>(rot, trans);
    // output projection
    gemm_abt<<<dim3(6, 12), 256>>>(pocat, w_out, b_out, out, 384, 2112);
}